// round 7
// baseline (speedup 1.0000x reference)
#include <cuda_runtime.h>
#include <math.h>
#include <stdint.h>

// ---------------------------------------------------------------------------
// Problem constants
// ---------------------------------------------------------------------------
#define BATCH   32
#define L_SER   32768
#define PATCH   32          // PS
#define DMODEL  256         // D
#define T_TOK   1024        // L / PS
#define QKV_N   768         // 3*D
#define ROWS    (BATCH * T_TOK)   // 32768 token rows

// ---------------------------------------------------------------------------
// Device scratch (static: no allocation allowed)
// ---------------------------------------------------------------------------
__device__ float  g_patches[BATCH * L_SER];                 // x_norm == patches, 4 MB
__device__ float  g_qkv[(size_t)ROWS * QKV_N];              // 96 MB
__device__ float  g_attnout[(size_t)ROWS * DMODEL];         // 32 MB
__device__ float  g_Weff[PATCH * QKV_N];                    // W_proj @ W_qkv
__device__ float  g_beff[QKV_N];
__device__ float  g_Wph[DMODEL * PATCH];                    // W_out @ W_head
__device__ float  g_bph[PATCH];
__device__ double g_loss_acc;

// ---------------------------------------------------------------------------
// K1: fold weights + zero loss accumulator
// ---------------------------------------------------------------------------
__global__ void prep_kernel(const float* __restrict__ Wproj, const float* __restrict__ bproj,
                            const float* __restrict__ Wqkv,  const float* __restrict__ bqkv,
                            const float* __restrict__ Wout,  const float* __restrict__ bout,
                            const float* __restrict__ Whead, const float* __restrict__ bhead)
{
    int idx = blockIdx.x * blockDim.x + threadIdx.x;
    if (idx == 0) g_loss_acc = 0.0;

    if (idx < PATCH * QKV_N) {
        int k = idx / QKV_N, j = idx % QKV_N;
        float acc = 0.f;
        #pragma unroll 8
        for (int d = 0; d < DMODEL; d++)
            acc = fmaf(Wproj[k * DMODEL + d], Wqkv[d * QKV_N + j], acc);
        g_Weff[idx] = acc;
    } else if (idx < PATCH * QKV_N + QKV_N) {
        int j = idx - PATCH * QKV_N;
        float acc = bqkv[j];
        #pragma unroll 8
        for (int d = 0; d < DMODEL; d++)
            acc = fmaf(bproj[d], Wqkv[d * QKV_N + j], acc);
        g_beff[j] = acc;
    } else if (idx < PATCH * QKV_N + QKV_N + DMODEL * PATCH) {
        int t = idx - (PATCH * QKV_N + QKV_N);
        int d = t / PATCH, p = t % PATCH;
        float acc = 0.f;
        #pragma unroll 8
        for (int e = 0; e < DMODEL; e++)
            acc = fmaf(Wout[d * DMODEL + e], Whead[e * PATCH + p], acc);
        g_Wph[t] = acc;
    } else if (idx < PATCH * QKV_N + QKV_N + DMODEL * PATCH + PATCH) {
        int p = idx - (PATCH * QKV_N + QKV_N + DMODEL * PATCH);
        float acc = bhead[p];
        #pragma unroll 8
        for (int e = 0; e < DMODEL; e++)
            acc = fmaf(bout[e], Whead[e * PATCH + p], acc);
        g_bph[p] = acc;
    }
}

// ---------------------------------------------------------------------------
// K2: instance norm over full series per batch row (ddof=1, +1e-5 on std)
// ---------------------------------------------------------------------------
__global__ void instnorm_kernel(const float* __restrict__ x)
{
    int b   = blockIdx.x;
    int tid = threadIdx.x;
    const float* xr = x + (size_t)b * L_SER;
    float*       pr = g_patches + (size_t)b * L_SER;

    float s = 0.f, ss = 0.f;
    for (int i = tid * 4; i < L_SER; i += 256 * 4) {
        float4 v = *(const float4*)(xr + i);
        s  += v.x + v.y + v.z + v.w;
        ss += v.x * v.x + v.y * v.y + v.z * v.z + v.w * v.w;
    }
    #pragma unroll
    for (int w = 16; w >= 1; w >>= 1) {
        s  += __shfl_xor_sync(0xffffffffu, s,  w);
        ss += __shfl_xor_sync(0xffffffffu, ss, w);
    }
    __shared__ float rs[8], rss[8];
    __shared__ float sh_mean, sh_inv;
    int lane = tid & 31, warp = tid >> 5;
    if (lane == 0) { rs[warp] = s; rss[warp] = ss; }
    __syncthreads();
    if (tid == 0) {
        float ts = 0.f, tss = 0.f;
        #pragma unroll
        for (int w = 0; w < 8; w++) { ts += rs[w]; tss += rss[w]; }
        float mean = ts / (float)L_SER;
        float var  = (tss - (float)L_SER * mean * mean) / (float)(L_SER - 1);
        float std  = sqrtf(var) + 1e-5f;
        sh_mean = mean;
        sh_inv  = 1.0f / std;
    }
    __syncthreads();
    float mean = sh_mean, inv = sh_inv;
    for (int i = tid * 4; i < L_SER; i += 256 * 4) {
        float4 v = *(const float4*)(xr + i);
        v.x = (v.x - mean) * inv; v.y = (v.y - mean) * inv;
        v.z = (v.z - mean) * inv; v.w = (v.w - mean) * inv;
        *(float4*)(pr + i) = v;
    }
}

// ---------------------------------------------------------------------------
// K3: qkv = patches[32768,32] @ Weff[32,768] + beff  (scalar, R4 version)
// ---------------------------------------------------------------------------
__global__ __launch_bounds__(256) void qkv_gemm_kernel()
{
    __shared__ __align__(16) float Ap[64][33];
    __shared__ __align__(16) float Bp[32][68];

    int tid = threadIdx.x;
    int ty  = tid >> 4, tx = tid & 15;
    int row0 = blockIdx.y * 64;
    int col0 = blockIdx.x * 64;

    for (int i = tid; i < 64 * 32; i += 256) {
        int r = i >> 5, k = i & 31;
        Ap[r][k] = g_patches[(size_t)(row0 + r) * PATCH + k];
    }
    for (int i = tid; i < 32 * 64; i += 256) {
        int k = i >> 6, c = i & 63;
        Bp[k][c] = g_Weff[k * QKV_N + col0 + c];
    }
    __syncthreads();

    float acc[4][4];
    #pragma unroll
    for (int i = 0; i < 4; i++)
        #pragma unroll
        for (int j = 0; j < 4; j++) acc[i][j] = 0.f;

    #pragma unroll
    for (int k = 0; k < 32; k++) {
        float a[4];
        #pragma unroll
        for (int i = 0; i < 4; i++) a[i] = Ap[ty * 4 + i][k];
        float4 b4 = *(const float4*)&Bp[k][tx * 4];
        #pragma unroll
        for (int i = 0; i < 4; i++) {
            acc[i][0] = fmaf(a[i], b4.x, acc[i][0]);
            acc[i][1] = fmaf(a[i], b4.y, acc[i][1]);
            acc[i][2] = fmaf(a[i], b4.z, acc[i][2]);
            acc[i][3] = fmaf(a[i], b4.w, acc[i][3]);
        }
    }

    float4 bias = *(const float4*)&g_beff[col0 + tx * 4];
    #pragma unroll
    for (int i = 0; i < 4; i++) {
        float4 o;
        o.x = acc[i][0] + bias.x; o.y = acc[i][1] + bias.y;
        o.z = acc[i][2] + bias.z; o.w = acc[i][3] + bias.w;
        *(float4*)(g_qkv + (size_t)(row0 + ty * 4 + i) * QKV_N + col0 + tx * 4) = o;
    }
}

// ---------------------------------------------------------------------------
// K4: causal flash attention, scalar fp32.
//   BM=BN=64, D=256. Q, K, V ALL fully resident in SMEM per j-iter
//   (217 KB total) -> only 2 __syncthreads + 1 __syncwarp per j-iter.
//   S-phase column mapping col = tx + 16*jj -> conflict-free Ks reads
//   (lane stride 260 floats = 4 banks apart, each 8-lane LDS.128 phase
//   tiles all 32 banks).
//   P rows are written and read by the same half-warp -> __syncwarp only.
// ---------------------------------------------------------------------------
#define SMS  260    // Q/K/V row stride in floats
#define PSS  68     // P row stride in floats
#define ATTN_SMEM ((3 * 64 * SMS + 64 * PSS) * 4)   // 217088 bytes

__global__ __launch_bounds__(256, 1) void attention_kernel()
{
    extern __shared__ __align__(16) float smem[];
    float* Qs = smem;                   // [64][260]
    float* Ks = Qs + 64 * SMS;          // [64][260]
    float* Vs = Ks + 64 * SMS;          // [64][260]
    float* Ps = Vs + 64 * SMS;          // [64][68]

    int tid = threadIdx.x;
    int ty  = tid >> 4, tx = tid & 15;
    int ty4 = ty * 4,  tx4 = tx * 4;
    int id  = blockIdx.x;
    int qb  = 15 - (id >> 5);           // heavy q-blocks launch first
    int b   = id & 31;

    // load Q block: 64 rows x 256 cols
    const float* qbase = g_qkv + ((size_t)b * T_TOK + qb * 64) * QKV_N;
    #pragma unroll
    for (int t = 0; t < 16; t++) {
        int idx = tid + t * 256;
        int r = idx >> 6, c4 = idx & 63;
        *(float4*)&Qs[r * SMS + c4 * 4] = *(const float4*)(qbase + (size_t)r * QKV_N + c4 * 4);
    }

    float m[4], l[4];
    float4 O[4][4];
    #pragma unroll
    for (int i = 0; i < 4; i++) {
        m[i] = -1e30f; l[i] = 0.f;
        #pragma unroll
        for (int dc = 0; dc < 4; dc++) O[i][dc] = make_float4(0.f, 0.f, 0.f, 0.f);
    }

    for (int j = 0; j <= qb; j++) {
        const float* kb = g_qkv + ((size_t)b * T_TOK + j * 64) * QKV_N + DMODEL;
        const float* vb = kb + DMODEL;

        __syncthreads();   // previous iter done reading K/V (and Q load visible, j=0)
        #pragma unroll
        for (int t = 0; t < 16; t++) {
            int idx = tid + t * 256;
            int r = idx >> 6, c4 = idx & 63;
            *(float4*)&Ks[r * SMS + c4 * 4] = *(const float4*)(kb + (size_t)r * QKV_N + c4 * 4);
        }
        #pragma unroll
        for (int t = 0; t < 16; t++) {
            int idx = tid + t * 256;
            int r = idx >> 6, c4 = idx & 63;
            *(float4*)&Vs[r * SMS + c4 * 4] = *(const float4*)(vb + (size_t)r * QKV_N + c4 * 4);
        }
        __syncthreads();   // K/V visible

        // ---- S = Q @ K^T, full 256 depth. col(jj) = tx + 16*jj ----
        float S[4][4];
        #pragma unroll
        for (int i = 0; i < 4; i++)
            #pragma unroll
            for (int jj = 0; jj < 4; jj++) S[i][jj] = 0.f;

        #pragma unroll 4
        for (int d = 0; d < 256; d += 4) {
            float4 qv[4], kv[4];
            #pragma unroll
            for (int i = 0; i < 4; i++)  qv[i]  = *(const float4*)&Qs[(ty4 + i) * SMS + d];
            #pragma unroll
            for (int jj = 0; jj < 4; jj++) kv[jj] = *(const float4*)&Ks[(tx + 16 * jj) * SMS + d];
            #pragma unroll
            for (int i = 0; i < 4; i++)
                #pragma unroll
                for (int jj = 0; jj < 4; jj++) {
                    S[i][jj] = fmaf(qv[i].x, kv[jj].x, S[i][jj]);
                    S[i][jj] = fmaf(qv[i].y, kv[jj].y, S[i][jj]);
                    S[i][jj] = fmaf(qv[i].z, kv[jj].z, S[i][jj]);
                    S[i][jj] = fmaf(qv[i].w, kv[jj].w, S[i][jj]);
                }
        }

        // ---- scale, causal mask, online softmax, write P (scalar) ----
        bool diag = (j == qb);
        #pragma unroll
        for (int i = 0; i < 4; i++) {
            int row = ty4 + i;
            float mx = -1e30f;
            #pragma unroll
            for (int jj = 0; jj < 4; jj++) {
                float s = S[i][jj] * 0.0625f;                    // 1/sqrt(256)
                if (diag && (tx + 16 * jj) > row) s = -1e30f;
                S[i][jj] = s;
                mx = fmaxf(mx, s);
            }
            #pragma unroll
            for (int w = 8; w >= 1; w >>= 1)
                mx = fmaxf(mx, __shfl_xor_sync(0xffffffffu, mx, w));
            float mnew  = fmaxf(m[i], mx);
            float alpha = __expf(m[i] - mnew);
            float ls = 0.f;
            #pragma unroll
            for (int jj = 0; jj < 4; jj++) {
                float p = __expf(S[i][jj] - mnew);
                Ps[row * PSS + tx + 16 * jj] = p;
                ls += p;
            }
            #pragma unroll
            for (int w = 8; w >= 1; w >>= 1)
                ls += __shfl_xor_sync(0xffffffffu, ls, w);
            l[i] = l[i] * alpha + ls;
            m[i] = mnew;
            #pragma unroll
            for (int dc = 0; dc < 4; dc++) {
                O[i][dc].x *= alpha; O[i][dc].y *= alpha;
                O[i][dc].z *= alpha; O[i][dc].w *= alpha;
            }
        }
        __syncwarp();      // P rows are produced & consumed by the same half-warp

        // ---- O += P @ V (V fully resident; thread cols = dc*64 + tx4) ----
        #pragma unroll
        for (int dc = 0; dc < 4; dc++) {
            #pragma unroll 4
            for (int s = 0; s < 64; s += 4) {
                float4 pv[4], vv[4];
                #pragma unroll
                for (int i = 0; i < 4; i++)  pv[i] = *(const float4*)&Ps[(ty4 + i) * PSS + s];
                #pragma unroll
                for (int ss = 0; ss < 4; ss++)
                    vv[ss] = *(const float4*)&Vs[(s + ss) * SMS + dc * 64 + tx4];
                #pragma unroll
                for (int i = 0; i < 4; i++) {
                    O[i][dc].x = fmaf(pv[i].x, vv[0].x, O[i][dc].x);
                    O[i][dc].x = fmaf(pv[i].y, vv[1].x, O[i][dc].x);
                    O[i][dc].x = fmaf(pv[i].z, vv[2].x, O[i][dc].x);
                    O[i][dc].x = fmaf(pv[i].w, vv[3].x, O[i][dc].x);
                    O[i][dc].y = fmaf(pv[i].x, vv[0].y, O[i][dc].y);
                    O[i][dc].y = fmaf(pv[i].y, vv[1].y, O[i][dc].y);
                    O[i][dc].y = fmaf(pv[i].z, vv[2].y, O[i][dc].y);
                    O[i][dc].y = fmaf(pv[i].w, vv[3].y, O[i][dc].y);
                    O[i][dc].z = fmaf(pv[i].x, vv[0].z, O[i][dc].z);
                    O[i][dc].z = fmaf(pv[i].y, vv[1].z, O[i][dc].z);
                    O[i][dc].z = fmaf(pv[i].z, vv[2].z, O[i][dc].z);
                    O[i][dc].z = fmaf(pv[i].w, vv[3].z, O[i][dc].z);
                    O[i][dc].w = fmaf(pv[i].x, vv[0].w, O[i][dc].w);
                    O[i][dc].w = fmaf(pv[i].y, vv[1].w, O[i][dc].w);
                    O[i][dc].w = fmaf(pv[i].z, vv[2].w, O[i][dc].w);
                    O[i][dc].w = fmaf(pv[i].w, vv[3].w, O[i][dc].w);
                }
            }
        }
    }

    // ---- normalize + store ----
    float* obase = g_attnout + ((size_t)b * T_TOK + qb * 64) * DMODEL;
    #pragma unroll
    for (int i = 0; i < 4; i++) {
        float inv = 1.0f / l[i];
        #pragma unroll
        for (int dc = 0; dc < 4; dc++) {
            float4 o = O[i][dc];
            o.x *= inv; o.y *= inv; o.z *= inv; o.w *= inv;
            *(float4*)(obase + (size_t)(ty4 + i) * DMODEL + dc * 64 + tx4) = o;
        }
    }
}

// ---------------------------------------------------------------------------
// K5: pred = attnout @ Wph + bph, fused next-patch MSE accumulation.
// ---------------------------------------------------------------------------
__global__ __launch_bounds__(256) void pred_loss_kernel()
{
    __shared__ float Ws[DMODEL * PATCH];
    int tid = threadIdx.x;
    for (int i = tid; i < DMODEL * PATCH; i += 256) Ws[i] = g_Wph[i];
    __syncthreads();

    int lane = tid & 31, warp = tid >> 5;
    int gw = blockIdx.x * 8 + warp;
    int nw = gridDim.x * 8;
    float bias = g_bph[lane];

    float lsum = 0.f;
    for (int row = gw; row < ROWS; row += nw) {
        const float* orow = g_attnout + (size_t)row * DMODEL;
        float acc = bias;
        #pragma unroll
        for (int kb = 0; kb < 8; kb++) {
            float ov = orow[kb * 32 + lane];
            #pragma unroll
            for (int k2 = 0; k2 < 32; k2++) {
                float o = __shfl_sync(0xffffffffu, ov, k2);
                acc = fmaf(o, Ws[(kb * 32 + k2) * 32 + lane], acc);
            }
        }
        if ((row & (T_TOK - 1)) != T_TOK - 1) {
            float d = acc - g_patches[(size_t)(row + 1) * PATCH + lane];
            lsum = fmaf(d, d, lsum);
        }
    }
    #pragma unroll
    for (int w = 16; w >= 1; w >>= 1)
        lsum += __shfl_xor_sync(0xffffffffu, lsum, w);
    if (lane == 0) atomicAdd(&g_loss_acc, (double)lsum);
}

// ---------------------------------------------------------------------------
// K6: finalize
// ---------------------------------------------------------------------------
__global__ void finalize_kernel(float* out)
{
    out[0] = (float)(g_loss_acc / (double)(BATCH * (T_TOK - 1) * PATCH));
}

// ---------------------------------------------------------------------------
// Launch
// ---------------------------------------------------------------------------
extern "C" void kernel_launch(void* const* d_in, const int* in_sizes, int n_in,
                              void* d_out, int out_size)
{
    const float* x      = (const float*)d_in[0];
    const float* Wproj  = (const float*)d_in[1];
    const float* bproj  = (const float*)d_in[2];
    const float* Wqkv   = (const float*)d_in[3];
    const float* bqkv   = (const float*)d_in[4];
    const float* Wout   = (const float*)d_in[5];
    const float* bout   = (const float*)d_in[6];
    const float* Whead  = (const float*)d_in[7];
    const float* bhead  = (const float*)d_in[8];
    float* out = (float*)d_out;

    cudaFuncSetAttribute(attention_kernel,
                         cudaFuncAttributeMaxDynamicSharedMemorySize, ATTN_SMEM);

    prep_kernel<<<132, 256>>>(Wproj, bproj, Wqkv, bqkv, Wout, bout, Whead, bhead);
    instnorm_kernel<<<BATCH, 256>>>(x);
    qkv_gemm_kernel<<<dim3(QKV_N / 64, ROWS / 64), 256>>>();
    attention_kernel<<<512, 256, ATTN_SMEM>>>();
    pred_loss_kernel<<<256, 256>>>();
    finalize_kernel<<<1, 1>>>(out);
}

// round 10
// speedup vs baseline: 3.0304x; 3.0304x over previous
#include <cuda_runtime.h>
#include <cuda_bf16.h>
#include <math.h>
#include <stdint.h>

// ---------------------------------------------------------------------------
// Problem constants
// ---------------------------------------------------------------------------
#define BATCH   32
#define L_SER   32768
#define PATCH   32
#define DMODEL  256
#define T_TOK   1024
#define QKV_N   768
#define ROWS    (BATCH * T_TOK)

// ---------------------------------------------------------------------------
// Device scratch
// ---------------------------------------------------------------------------
__device__ float          g_patches[BATCH * L_SER];             // fp32 (MSE targets)
__device__ __nv_bfloat16  g_qkvh[(size_t)ROWS * QKV_N];         // 48 MB bf16 qkv
__device__ __nv_bfloat16  g_vwT[(size_t)BATCH * PATCH * T_TOK]; // (V@Wph)^T  [b][p][t]
__device__ float          g_Weff[PATCH * QKV_N];
__device__ float          g_beff[QKV_N];
__device__ float          g_Wph[DMODEL * PATCH];
__device__ float          g_bph[PATCH];
__device__ double         g_loss_acc;

// ---------------------------------------------------------------------------
// mma.sync / ldmatrix helpers (sm_80-era PTX — compiles on plain sm_103)
// ---------------------------------------------------------------------------
__device__ __forceinline__ uint32_t s2u(const void* p) {
    return (uint32_t)__cvta_generic_to_shared(p);
}
__device__ __forceinline__ void ldsm4(uint32_t* r, uint32_t a) {
    asm volatile("ldmatrix.sync.aligned.m8n8.x4.shared.b16 {%0,%1,%2,%3}, [%4];"
                 : "=r"(r[0]), "=r"(r[1]), "=r"(r[2]), "=r"(r[3]) : "r"(a));
}
__device__ __forceinline__ void mma16816(float* c, const uint32_t* a, uint32_t b0, uint32_t b1) {
    asm volatile("mma.sync.aligned.m16n8k16.row.col.f32.bf16.bf16.f32 "
                 "{%0,%1,%2,%3}, {%4,%5,%6,%7}, {%8,%9}, {%0,%1,%2,%3};"
                 : "+f"(c[0]), "+f"(c[1]), "+f"(c[2]), "+f"(c[3])
                 : "r"(a[0]), "r"(a[1]), "r"(a[2]), "r"(a[3]), "r"(b0), "r"(b1));
}
__device__ __forceinline__ uint32_t packbf2(float x, float y) {
    __nv_bfloat162 h = __float22bfloat162_rn(make_float2(x, y));
    return *(uint32_t*)&h;
}

// ---------------------------------------------------------------------------
// K1: fold weights + zero loss accumulator
// ---------------------------------------------------------------------------
__global__ void prep_kernel(const float* __restrict__ Wproj, const float* __restrict__ bproj,
                            const float* __restrict__ Wqkv,  const float* __restrict__ bqkv,
                            const float* __restrict__ Wout,  const float* __restrict__ bout,
                            const float* __restrict__ Whead, const float* __restrict__ bhead)
{
    int idx = blockIdx.x * blockDim.x + threadIdx.x;
    if (idx == 0) g_loss_acc = 0.0;

    if (idx < PATCH * QKV_N) {
        int k = idx / QKV_N, j = idx % QKV_N;
        float acc = 0.f;
        #pragma unroll 8
        for (int d = 0; d < DMODEL; d++)
            acc = fmaf(Wproj[k * DMODEL + d], Wqkv[d * QKV_N + j], acc);
        g_Weff[idx] = acc;
    } else if (idx < PATCH * QKV_N + QKV_N) {
        int j = idx - PATCH * QKV_N;
        float acc = bqkv[j];
        #pragma unroll 8
        for (int d = 0; d < DMODEL; d++)
            acc = fmaf(bproj[d], Wqkv[d * QKV_N + j], acc);
        g_beff[j] = acc;
    } else if (idx < PATCH * QKV_N + QKV_N + DMODEL * PATCH) {
        int t = idx - (PATCH * QKV_N + QKV_N);
        int d = t / PATCH, p = t % PATCH;
        float acc = 0.f;
        #pragma unroll 8
        for (int e = 0; e < DMODEL; e++)
            acc = fmaf(Wout[d * DMODEL + e], Whead[e * PATCH + p], acc);
        g_Wph[t] = acc;
    } else if (idx < PATCH * QKV_N + QKV_N + DMODEL * PATCH + PATCH) {
        int p = idx - (PATCH * QKV_N + QKV_N + DMODEL * PATCH);
        float acc = bhead[p];
        #pragma unroll 8
        for (int e = 0; e < DMODEL; e++)
            acc = fmaf(bout[e], Whead[e * PATCH + p], acc);
        g_bph[p] = acc;
    }
}

// ---------------------------------------------------------------------------
// K2: instance norm (ddof=1, +1e-5 on std)
// ---------------------------------------------------------------------------
__global__ __launch_bounds__(1024) void instnorm_kernel(const float* __restrict__ x)
{
    int b   = blockIdx.x;
    int tid = threadIdx.x;
    const float* xr = x + (size_t)b * L_SER;
    float*       pr = g_patches + (size_t)b * L_SER;

    float s = 0.f, ss = 0.f;
    for (int i = tid * 4; i < L_SER; i += 4096) {
        float4 v = *(const float4*)(xr + i);
        s  += v.x + v.y + v.z + v.w;
        ss += v.x * v.x + v.y * v.y + v.z * v.z + v.w * v.w;
    }
    #pragma unroll
    for (int w = 16; w >= 1; w >>= 1) {
        s  += __shfl_xor_sync(0xffffffffu, s,  w);
        ss += __shfl_xor_sync(0xffffffffu, ss, w);
    }
    __shared__ float rs[32], rss[32];
    __shared__ float sh_mean, sh_inv;
    int lane = tid & 31, warp = tid >> 5;
    if (lane == 0) { rs[warp] = s; rss[warp] = ss; }
    __syncthreads();
    if (tid == 0) {
        float ts = 0.f, tss = 0.f;
        #pragma unroll
        for (int w = 0; w < 32; w++) { ts += rs[w]; tss += rss[w]; }
        float mean = ts / (float)L_SER;
        float var  = (tss - (float)L_SER * mean * mean) / (float)(L_SER - 1);
        sh_mean = mean;
        sh_inv  = 1.0f / (sqrtf(var) + 1e-5f);
    }
    __syncthreads();
    float mean = sh_mean, inv = sh_inv;
    for (int i = tid * 4; i < L_SER; i += 4096) {
        float4 v = *(const float4*)(xr + i);
        v.x = (v.x - mean) * inv; v.y = (v.y - mean) * inv;
        v.z = (v.z - mean) * inv; v.w = (v.w - mean) * inv;
        *(float4*)(pr + i) = v;
    }
}

// ---------------------------------------------------------------------------
// K3: qkv = patches @ Weff + beff  -> bf16
// ---------------------------------------------------------------------------
__global__ __launch_bounds__(256) void qkv_gemm_kernel()
{
    __shared__ __align__(16) float Ap[64][33];
    __shared__ __align__(16) float Bp[32][68];

    int tid = threadIdx.x;
    int ty  = tid >> 4, tx = tid & 15;
    int row0 = blockIdx.y * 64;
    int col0 = blockIdx.x * 64;

    for (int i = tid; i < 64 * 32; i += 256) {
        int r = i >> 5, k = i & 31;
        Ap[r][k] = g_patches[(size_t)(row0 + r) * PATCH + k];
    }
    for (int i = tid; i < 32 * 64; i += 256) {
        int k = i >> 6, c = i & 63;
        Bp[k][c] = g_Weff[k * QKV_N + col0 + c];
    }
    __syncthreads();

    float acc[4][4];
    #pragma unroll
    for (int i = 0; i < 4; i++)
        #pragma unroll
        for (int j = 0; j < 4; j++) acc[i][j] = 0.f;

    #pragma unroll
    for (int k = 0; k < 32; k++) {
        float a[4];
        #pragma unroll
        for (int i = 0; i < 4; i++) a[i] = Ap[ty * 4 + i][k];
        float4 b4 = *(const float4*)&Bp[k][tx * 4];
        #pragma unroll
        for (int i = 0; i < 4; i++) {
            acc[i][0] = fmaf(a[i], b4.x, acc[i][0]);
            acc[i][1] = fmaf(a[i], b4.y, acc[i][1]);
            acc[i][2] = fmaf(a[i], b4.z, acc[i][2]);
            acc[i][3] = fmaf(a[i], b4.w, acc[i][3]);
        }
    }

    float4 bias = *(const float4*)&g_beff[col0 + tx * 4];
    #pragma unroll
    for (int i = 0; i < 4; i++) {
        uint2 st;
        st.x = packbf2(acc[i][0] + bias.x, acc[i][1] + bias.y);
        st.y = packbf2(acc[i][2] + bias.z, acc[i][3] + bias.w);
        *(uint2*)(g_qkvh + (size_t)(row0 + ty * 4 + i) * QKV_N + col0 + tx * 4) = st;
    }
}

// ---------------------------------------------------------------------------
// K3b: VW^T[b][p][t] = (V[b,t] @ Wph)[p]   (warp-per-row shuffle GEMV)
// ---------------------------------------------------------------------------
__global__ __launch_bounds__(256) void vw_kernel()
{
    __shared__ float Ws[DMODEL * PATCH];
    int tid = threadIdx.x;
    for (int i = tid; i < DMODEL * PATCH; i += 256) Ws[i] = g_Wph[i];
    __syncthreads();

    int lane = tid & 31, warp = tid >> 5;
    int gw = blockIdx.x * 8 + warp;
    int nw = gridDim.x * 8;

    for (int row = gw; row < ROWS; row += nw) {
        const __nv_bfloat16* vrow = g_qkvh + (size_t)row * QKV_N + 512;
        uint4 vv = *(const uint4*)(vrow + lane * 8);
        float acc = 0.f;
        #pragma unroll 4
        for (int src = 0; src < 32; src++) {
            uint4 t;
            t.x = __shfl_sync(0xffffffffu, vv.x, src);
            t.y = __shfl_sync(0xffffffffu, vv.y, src);
            t.z = __shfl_sync(0xffffffffu, vv.z, src);
            t.w = __shfl_sync(0xffffffffu, vv.w, src);
            const uint32_t* tw = (const uint32_t*)&t;
            #pragma unroll
            for (int q = 0; q < 4; q++) {
                float2 f = __bfloat1622float2(*(const __nv_bfloat162*)&tw[q]);
                int d = src * 8 + q * 2;
                acc = fmaf(f.x, Ws[d * 32 + lane], acc);
                acc = fmaf(f.y, Ws[(d + 1) * 32 + lane], acc);
            }
        }
        int b = row >> 10, t = row & 1023;
        g_vwT[((size_t)b * PATCH + lane) * T_TOK + t] = __float2bfloat16_rn(acc);
    }
}

// ---------------------------------------------------------------------------
// K4: mma.sync bf16 causal attention, BM=128, BN=64, fused head + MSE.
//   Grid 256 = (8 qb heavy-first) x (32 batch), 8 warps.
//   Warp w owns rows 16w..16w+15. S via m16n8k16; P stays in registers
//   (C-layout == A-layout identity); PV has N=32 (VW fold).
//   Fixed-offset softmax: p = exp(s/16 - 12)  == softmax after /l.
// ---------------------------------------------------------------------------
#define QSTR 264          // bf16 row stride (528 B): ldmatrix conflict-free
#define VWSTR 72
#define ATTN_SMEM_BYTES (((128 + 64) * QSTR + 32 * VWSTR) * 2 + 128)

__global__ __launch_bounds__(256) void attention_kernel()
{
    extern __shared__ __align__(16) __nv_bfloat16 smh[];
    __nv_bfloat16* Qs  = smh;                       // [128][QSTR]
    __nv_bfloat16* Ks  = Qs + 128 * QSTR;           // [64][QSTR]
    __nv_bfloat16* VWs = Ks + 64 * QSTR;            // [32][VWSTR]
    float* red = (float*)(VWs + 32 * VWSTR);

    int tid  = threadIdx.x;
    int w    = tid >> 5, lane = tid & 31;
    int qb   = 7 - (blockIdx.x >> 5);               // heavy q-blocks first
    int b    = blockIdx.x & 31;

    // ---- load Q [128,256] ----
    const __nv_bfloat16* qg = g_qkvh + ((size_t)b * T_TOK + qb * 128) * QKV_N;
    #pragma unroll
    for (int t = 0; t < 16; t++) {
        int idx = tid + t * 256;
        int r = idx >> 5, c = idx & 31;
        *(uint4*)&Qs[r * QSTR + c * 8] = *(const uint4*)(qg + (size_t)r * QKV_N + c * 8);
    }

    // ldmatrix base addresses (byte offsets added per step)
    uint32_t qaddr = s2u(&Qs[(16 * w + (lane & 15)) * QSTR + ((lane >> 4) << 3)]);
    uint32_t kaddr = s2u(&Ks[((lane & 7) + ((lane >> 4) << 3)) * QSTR + (((lane >> 3) & 1) << 3)]);
    uint32_t vaddr = s2u(&VWs[((lane & 7) + ((lane >> 4) << 3)) * VWSTR + (((lane >> 3) & 1) << 3)]);

    float po[4][4];
    #pragma unroll
    for (int i = 0; i < 4; i++)
        #pragma unroll
        for (int k = 0; k < 4; k++) po[i][k] = 0.f;
    float l0 = 0.f, l1 = 0.f;

    int g     = lane >> 2;
    int colp  = (lane & 3) * 2;
    int trow0 = qb * 128 + 16 * w + g;
    int trow1 = trow0 + 8;

    const __nv_bfloat16* kgbase = g_qkvh + ((size_t)b * T_TOK) * QKV_N + 256;
    const __nv_bfloat16* vwbase = g_vwT + (size_t)b * PATCH * T_TOK;

    int jmax = 2 * qb + 1;
    for (int j = 0; j <= jmax; j++) {
        __syncthreads();               // prev iter done reading Ks/VWs (covers Q store, j=0)
        const __nv_bfloat16* kg = kgbase + (size_t)j * 64 * QKV_N;
        #pragma unroll
        for (int t = 0; t < 8; t++) {
            int idx = tid + t * 256;
            int r = idx >> 5, c = idx & 31;
            *(uint4*)&Ks[r * QSTR + c * 8] = *(const uint4*)(kg + (size_t)r * QKV_N + c * 8);
        }
        {
            int p = tid >> 3, u = tid & 7;
            *(uint4*)&VWs[p * VWSTR + u * 8] =
                *(const uint4*)(vwbase + (size_t)p * T_TOK + j * 64 + u * 8);
        }
        __syncthreads();

        // ---- S = Q @ K^T : sc[8 ntiles][4] ----
        float sc[8][4];
        #pragma unroll
        for (int nt = 0; nt < 8; nt++)
            #pragma unroll
            for (int k = 0; k < 4; k++) sc[nt][k] = 0.f;

        #pragma unroll
        for (int ks = 0; ks < 16; ks++) {
            uint32_t qa[4];
            ldsm4(qa, qaddr + ks * 32);
            #pragma unroll
            for (int nt2 = 0; nt2 < 4; nt2++) {
                uint32_t kb[4];
                ldsm4(kb, kaddr + nt2 * (16 * QSTR * 2) + ks * 32);
                mma16816(sc[2 * nt2],     qa, kb[0], kb[1]);
                mma16816(sc[2 * nt2 + 1], qa, kb[2], kb[3]);
            }
        }

        // ---- fixed-offset softmax + pack P into A-fragments ----
        uint32_t pa[4][4];
        int keyb = j * 64;
        #pragma unroll
        for (int nt = 0; nt < 8; nt++) {
            int k0 = keyb + nt * 8 + colp;
            float p0 = (k0     <= trow0) ? __expf(sc[nt][0] * 0.0625f - 12.0f) : 0.f;
            float p1 = (k0 + 1 <= trow0) ? __expf(sc[nt][1] * 0.0625f - 12.0f) : 0.f;
            float p2 = (k0     <= trow1) ? __expf(sc[nt][2] * 0.0625f - 12.0f) : 0.f;
            float p3 = (k0 + 1 <= trow1) ? __expf(sc[nt][3] * 0.0625f - 12.0f) : 0.f;
            l0 += p0 + p1;
            l1 += p2 + p3;
            int ks = nt >> 1, h = (nt & 1) * 2;
            pa[ks][h]     = packbf2(p0, p1);
            pa[ks][h + 1] = packbf2(p2, p3);
        }

        // ---- predraw += P @ VW : N=32 ----
        #pragma unroll
        for (int ks = 0; ks < 4; ks++) {
            #pragma unroll
            for (int pt2 = 0; pt2 < 2; pt2++) {
                uint32_t vb[4];
                ldsm4(vb, vaddr + pt2 * (16 * VWSTR * 2) + ks * 32);
                mma16816(po[2 * pt2],     pa[ks], vb[0], vb[1]);
                mma16816(po[2 * pt2 + 1], pa[ks], vb[2], vb[3]);
            }
        }
    }

    // ---- epilogue: row sums, pred, MSE ----
    l0 += __shfl_xor_sync(0xffffffffu, l0, 1);
    l0 += __shfl_xor_sync(0xffffffffu, l0, 2);
    l1 += __shfl_xor_sync(0xffffffffu, l1, 1);
    l1 += __shfl_xor_sync(0xffffffffu, l1, 2);
    float linv0 = 1.0f / l0, linv1 = 1.0f / l1;

    const float* pbase = g_patches + (size_t)b * L_SER;
    float lsum = 0.f;
    if (trow0 < T_TOK - 1) {
        const float* tgt = pbase + (size_t)(trow0 + 1) * PATCH;
        #pragma unroll
        for (int nt = 0; nt < 4; nt++) {
            int pc = nt * 8 + colp;
            float d0 = po[nt][0] * linv0 + g_bph[pc]     - tgt[pc];
            float d1 = po[nt][1] * linv0 + g_bph[pc + 1] - tgt[pc + 1];
            lsum = fmaf(d0, d0, lsum);
            lsum = fmaf(d1, d1, lsum);
        }
    }
    if (trow1 < T_TOK - 1) {
        const float* tgt = pbase + (size_t)(trow1 + 1) * PATCH;
        #pragma unroll
        for (int nt = 0; nt < 4; nt++) {
            int pc = nt * 8 + colp;
            float d0 = po[nt][2] * linv1 + g_bph[pc]     - tgt[pc];
            float d1 = po[nt][3] * linv1 + g_bph[pc + 1] - tgt[pc + 1];
            lsum = fmaf(d0, d0, lsum);
            lsum = fmaf(d1, d1, lsum);
        }
    }
    #pragma unroll
    for (int s = 16; s >= 1; s >>= 1)
        lsum += __shfl_xor_sync(0xffffffffu, lsum, s);
    if (lane == 0) red[w] = lsum;
    __syncthreads();
    if (tid == 0) {
        float t = 0.f;
        #pragma unroll
        for (int i = 0; i < 8; i++) t += red[i];
        atomicAdd(&g_loss_acc, (double)t);
    }
}

// ---------------------------------------------------------------------------
// K6: finalize
// ---------------------------------------------------------------------------
__global__ void finalize_kernel(float* out)
{
    out[0] = (float)(g_loss_acc / (double)(BATCH * (T_TOK - 1) * PATCH));
}

// ---------------------------------------------------------------------------
// Launch
// ---------------------------------------------------------------------------
extern "C" void kernel_launch(void* const* d_in, const int* in_sizes, int n_in,
                              void* d_out, int out_size)
{
    const float* x      = (const float*)d_in[0];
    const float* Wproj  = (const float*)d_in[1];
    const float* bproj  = (const float*)d_in[2];
    const float* Wqkv   = (const float*)d_in[3];
    const float* bqkv   = (const float*)d_in[4];
    const float* Wout   = (const float*)d_in[5];
    const float* bout   = (const float*)d_in[6];
    const float* Whead  = (const float*)d_in[7];
    const float* bhead  = (const float*)d_in[8];
    float* out = (float*)d_out;

    cudaFuncSetAttribute(attention_kernel,
                         cudaFuncAttributeMaxDynamicSharedMemorySize, ATTN_SMEM_BYTES);

    prep_kernel<<<132, 256>>>(Wproj, bproj, Wqkv, bqkv, Wout, bout, Whead, bhead);
    instnorm_kernel<<<BATCH, 1024>>>(x);
    qkv_gemm_kernel<<<dim3(QKV_N / 64, ROWS / 64), 256>>>();
    vw_kernel<<<256, 256>>>();
    attention_kernel<<<256, 256, ATTN_SMEM_BYTES>>>();
    finalize_kernel<<<1, 1>>>(out);
}

// round 11
// speedup vs baseline: 4.5594x; 1.5045x over previous
#include <cuda_runtime.h>
#include <cuda_bf16.h>
#include <math.h>
#include <stdint.h>

// ---------------------------------------------------------------------------
// Problem constants
// ---------------------------------------------------------------------------
#define BATCH   32
#define L_SER   32768
#define PATCH   32
#define DMODEL  256
#define T_TOK   1024
#define QKV_N   768
#define QKS     512            // Q,K row stride in g_qkvh (V eliminated)
#define ROWS    (BATCH * T_TOK)

// ---------------------------------------------------------------------------
// Device scratch
// ---------------------------------------------------------------------------
__device__ float          g_patches[BATCH * L_SER];          // fp32 (MSE targets)
__device__ __nv_bfloat16  g_qkvh[(size_t)ROWS * QKS];        // 32 MB bf16 Q|K
__device__ __nv_bfloat16  g_vw[(size_t)ROWS * PATCH];        // 2 MB  VW [t][p]
__device__ float          g_Weff[PATCH * QKV_N];             // W_proj @ W_qkv (full, incl V part)
__device__ float          g_beff[QKV_N];
__device__ float          g_Wph[DMODEL * PATCH];             // W_out @ W_head
__device__ float          g_bph[PATCH];
__device__ float          g_Wvw[PATCH * PATCH];              // Weff_v @ Wph
__device__ float          g_bvw[PATCH];                      // beff_v @ Wph
__device__ double         g_stats[2 * BATCH];                // per-b sum, sumsq
__device__ double         g_loss_acc;

// ---------------------------------------------------------------------------
// mma.sync / ldmatrix helpers (sm_80-era PTX — compiles on plain sm_103)
// ---------------------------------------------------------------------------
__device__ __forceinline__ uint32_t s2u(const void* p) {
    return (uint32_t)__cvta_generic_to_shared(p);
}
__device__ __forceinline__ void ldsm4(uint32_t* r, uint32_t a) {
    asm volatile("ldmatrix.sync.aligned.m8n8.x4.shared.b16 {%0,%1,%2,%3}, [%4];"
                 : "=r"(r[0]), "=r"(r[1]), "=r"(r[2]), "=r"(r[3]) : "r"(a));
}
__device__ __forceinline__ void ldsm4t(uint32_t* r, uint32_t a) {
    asm volatile("ldmatrix.sync.aligned.m8n8.x4.trans.shared.b16 {%0,%1,%2,%3}, [%4];"
                 : "=r"(r[0]), "=r"(r[1]), "=r"(r[2]), "=r"(r[3]) : "r"(a));
}
__device__ __forceinline__ void mma16816(float* c, const uint32_t* a, uint32_t b0, uint32_t b1) {
    asm volatile("mma.sync.aligned.m16n8k16.row.col.f32.bf16.bf16.f32 "
                 "{%0,%1,%2,%3}, {%4,%5,%6,%7}, {%8,%9}, {%0,%1,%2,%3};"
                 : "+f"(c[0]), "+f"(c[1]), "+f"(c[2]), "+f"(c[3])
                 : "r"(a[0]), "r"(a[1]), "r"(a[2]), "r"(a[3]), "r"(b0), "r"(b1));
}
__device__ __forceinline__ uint32_t packbf2(float x, float y) {
    __nv_bfloat162 h = __float22bfloat162_rn(make_float2(x, y));
    return *(uint32_t*)&h;
}

// ---------------------------------------------------------------------------
// K1: fold weights + zero accumulators
// ---------------------------------------------------------------------------
__global__ void prep_kernel(const float* __restrict__ Wproj, const float* __restrict__ bproj,
                            const float* __restrict__ Wqkv,  const float* __restrict__ bqkv,
                            const float* __restrict__ Wout,  const float* __restrict__ bout,
                            const float* __restrict__ Whead, const float* __restrict__ bhead)
{
    int idx = blockIdx.x * blockDim.x + threadIdx.x;
    if (idx == 0) g_loss_acc = 0.0;
    if (idx < 2 * BATCH) g_stats[idx] = 0.0;

    if (idx < PATCH * QKV_N) {
        int k = idx / QKV_N, j = idx % QKV_N;
        float acc = 0.f;
        #pragma unroll 8
        for (int d = 0; d < DMODEL; d++)
            acc = fmaf(Wproj[k * DMODEL + d], Wqkv[d * QKV_N + j], acc);
        g_Weff[idx] = acc;
    } else if (idx < PATCH * QKV_N + QKV_N) {
        int j = idx - PATCH * QKV_N;
        float acc = bqkv[j];
        #pragma unroll 8
        for (int d = 0; d < DMODEL; d++)
            acc = fmaf(bproj[d], Wqkv[d * QKV_N + j], acc);
        g_beff[j] = acc;
    } else if (idx < PATCH * QKV_N + QKV_N + DMODEL * PATCH) {
        int t = idx - (PATCH * QKV_N + QKV_N);
        int d = t / PATCH, p = t % PATCH;
        float acc = 0.f;
        #pragma unroll 8
        for (int e = 0; e < DMODEL; e++)
            acc = fmaf(Wout[d * DMODEL + e], Whead[e * PATCH + p], acc);
        g_Wph[t] = acc;
    } else if (idx < PATCH * QKV_N + QKV_N + DMODEL * PATCH + PATCH) {
        int p = idx - (PATCH * QKV_N + QKV_N + DMODEL * PATCH);
        float acc = bhead[p];
        #pragma unroll 8
        for (int e = 0; e < DMODEL; e++)
            acc = fmaf(bout[e], Whead[e * PATCH + p], acc);
        g_bph[p] = acc;
    }
}

// ---------------------------------------------------------------------------
// K1b: Wvw = Weff[:,512:768] @ Wph;  bvw = beff[512:] @ Wph
// ---------------------------------------------------------------------------
__global__ __launch_bounds__(1024) void prep2_kernel()
{
    int tid = threadIdx.x;
    int k = tid >> 5, p = tid & 31;
    float acc = 0.f;
    #pragma unroll 8
    for (int d = 0; d < DMODEL; d++)
        acc = fmaf(g_Weff[k * QKV_N + 512 + d], g_Wph[d * PATCH + p], acc);
    g_Wvw[k * PATCH + p] = acc;
    if (tid < PATCH) {
        float b = 0.f;
        #pragma unroll 8
        for (int d = 0; d < DMODEL; d++)
            b = fmaf(g_beff[512 + d], g_Wph[d * PATCH + tid], b);
        g_bvw[tid] = b;
    }
}

// ---------------------------------------------------------------------------
// K2a/K2b: two-pass instance norm over 128 CTAs (4 per batch row)
// ---------------------------------------------------------------------------
__global__ __launch_bounds__(256) void instnorm_stats(const float* __restrict__ x)
{
    int b = blockIdx.x >> 2, part = blockIdx.x & 3;
    int tid = threadIdx.x;
    const float* xr = x + (size_t)b * L_SER + part * 8192;

    float s = 0.f, ss = 0.f;
    #pragma unroll
    for (int t = 0; t < 8; t++) {
        float4 v = *(const float4*)(xr + tid * 4 + t * 1024);
        s  += v.x + v.y + v.z + v.w;
        ss += v.x * v.x + v.y * v.y + v.z * v.z + v.w * v.w;
    }
    #pragma unroll
    for (int w = 16; w >= 1; w >>= 1) {
        s  += __shfl_xor_sync(0xffffffffu, s,  w);
        ss += __shfl_xor_sync(0xffffffffu, ss, w);
    }
    __shared__ float rs[8], rss[8];
    int lane = tid & 31, warp = tid >> 5;
    if (lane == 0) { rs[warp] = s; rss[warp] = ss; }
    __syncthreads();
    if (tid == 0) {
        float ts = 0.f, tss = 0.f;
        #pragma unroll
        for (int w = 0; w < 8; w++) { ts += rs[w]; tss += rss[w]; }
        atomicAdd(&g_stats[2 * b],     (double)ts);
        atomicAdd(&g_stats[2 * b + 1], (double)tss);
    }
}

__global__ __launch_bounds__(256) void instnorm_apply(const float* __restrict__ x)
{
    int b = blockIdx.x >> 2, part = blockIdx.x & 3;
    int tid = threadIdx.x;
    double s  = g_stats[2 * b];
    double ss = g_stats[2 * b + 1];
    double meand = s / (double)L_SER;
    double vard  = (ss - (double)L_SER * meand * meand) / (double)(L_SER - 1);
    float mean = (float)meand;
    float inv  = 1.0f / ((float)sqrt(vard) + 1e-5f);

    const float* xr = x + (size_t)b * L_SER + part * 8192;
    float*       pr = g_patches + (size_t)b * L_SER + part * 8192;
    #pragma unroll
    for (int t = 0; t < 8; t++) {
        float4 v = *(const float4*)(xr + tid * 4 + t * 1024);
        v.x = (v.x - mean) * inv; v.y = (v.y - mean) * inv;
        v.z = (v.z - mean) * inv; v.w = (v.w - mean) * inv;
        *(float4*)(pr + tid * 4 + t * 1024) = v;
    }
}

// ---------------------------------------------------------------------------
// K3: [Q|K|VW] = patches @ [Weff_qk | Wvw] + bias  -> bf16
//   grid.x: blocks 0-7 -> Q,K cols (Weff), block 8 -> VW (Wvw, 32 cols)
// ---------------------------------------------------------------------------
__global__ __launch_bounds__(256) void qkv_gemm_kernel()
{
    __shared__ __align__(16) float Ap[64][33];
    __shared__ __align__(16) float Bp[32][68];

    int tid = threadIdx.x;
    int ty  = tid >> 4, tx = tid & 15;
    int row0 = blockIdx.y * 64;
    bool vwblk = (blockIdx.x == 8);
    int col0 = blockIdx.x * 64;

    for (int i = tid; i < 64 * 32; i += 256) {
        int r = i >> 5, k = i & 31;
        Ap[r][k] = g_patches[(size_t)(row0 + r) * PATCH + k];
    }
    for (int i = tid; i < 32 * 64; i += 256) {
        int k = i >> 6, c = i & 63;
        Bp[k][c] = vwblk ? (c < 32 ? g_Wvw[k * PATCH + c] : 0.f)
                         : g_Weff[k * QKV_N + col0 + c];
    }
    __syncthreads();

    float acc[4][4];
    #pragma unroll
    for (int i = 0; i < 4; i++)
        #pragma unroll
        for (int j = 0; j < 4; j++) acc[i][j] = 0.f;

    #pragma unroll
    for (int k = 0; k < 32; k++) {
        float a[4];
        #pragma unroll
        for (int i = 0; i < 4; i++) a[i] = Ap[ty * 4 + i][k];
        float4 b4 = *(const float4*)&Bp[k][tx * 4];
        #pragma unroll
        for (int i = 0; i < 4; i++) {
            acc[i][0] = fmaf(a[i], b4.x, acc[i][0]);
            acc[i][1] = fmaf(a[i], b4.y, acc[i][1]);
            acc[i][2] = fmaf(a[i], b4.z, acc[i][2]);
            acc[i][3] = fmaf(a[i], b4.w, acc[i][3]);
        }
    }

    if (vwblk) {
        if (tx < 8) {
            float4 bias = *(const float4*)&g_bvw[tx * 4];
            #pragma unroll
            for (int i = 0; i < 4; i++) {
                uint2 st;
                st.x = packbf2(acc[i][0] + bias.x, acc[i][1] + bias.y);
                st.y = packbf2(acc[i][2] + bias.z, acc[i][3] + bias.w);
                *(uint2*)(g_vw + (size_t)(row0 + ty * 4 + i) * PATCH + tx * 4) = st;
            }
        }
    } else {
        float4 bias = *(const float4*)&g_beff[col0 + tx * 4];
        #pragma unroll
        for (int i = 0; i < 4; i++) {
            uint2 st;
            st.x = packbf2(acc[i][0] + bias.x, acc[i][1] + bias.y);
            st.y = packbf2(acc[i][2] + bias.z, acc[i][3] + bias.w);
            *(uint2*)(g_qkvh + (size_t)(row0 + ty * 4 + i) * QKS + col0 + tx * 4) = st;
        }
    }
}

// ---------------------------------------------------------------------------
// K4: mma.sync bf16 causal attention, BM=128, BN=64, fused head + MSE.
//   VW tile [64 t][32 p] row-major in SMEM (stride 40), B-frags via
//   ldmatrix.x4.trans. 2 CTAs/SM (213 KB SMEM total).
// ---------------------------------------------------------------------------
#define QSTR  264         // Q/K bf16 row stride: ldmatrix conflict-free
#define VWSTR 40          // VW bf16 row stride (80 B): conflict-free trans loads
#define ATTN_SMEM_BYTES (((128 + 64) * QSTR + 64 * VWSTR) * 2 + 128)

__global__ __launch_bounds__(256, 2) void attention_kernel()
{
    extern __shared__ __align__(16) __nv_bfloat16 smh[];
    __nv_bfloat16* Qs  = smh;                       // [128][QSTR]
    __nv_bfloat16* Ks  = Qs + 128 * QSTR;           // [64][QSTR]
    __nv_bfloat16* VWs = Ks + 64 * QSTR;            // [64][VWSTR]
    float* red = (float*)(VWs + 64 * VWSTR);

    int tid  = threadIdx.x;
    int w    = tid >> 5, lane = tid & 31;
    int qb   = 7 - (blockIdx.x >> 5);               // heavy q-blocks first
    int b    = blockIdx.x & 31;

    // ---- load Q [128,256] ----
    const __nv_bfloat16* qg = g_qkvh + ((size_t)b * T_TOK + qb * 128) * QKS;
    #pragma unroll
    for (int t = 0; t < 16; t++) {
        int idx = tid + t * 256;
        int r = idx >> 5, c = idx & 31;
        *(uint4*)&Qs[r * QSTR + c * 8] = *(const uint4*)(qg + (size_t)r * QKS + c * 8);
    }

    uint32_t qaddr = s2u(&Qs[(16 * w + (lane & 15)) * QSTR + ((lane >> 4) << 3)]);
    uint32_t kaddr = s2u(&Ks[((lane & 7) + ((lane >> 4) << 3)) * QSTR + (((lane >> 3) & 1) << 3)]);
    // trans: lanes 0-7 -> k rows 0-7 (p0), 8-15 -> k 8-15 (p0), 16-23 -> k 0-7 (p8), 24-31 -> k 8-15 (p8)
    uint32_t vaddr = s2u(&VWs[((lane & 7) + (((lane >> 3) & 1) << 3)) * VWSTR + ((lane >> 4) << 3)]);

    float po[4][4];
    #pragma unroll
    for (int i = 0; i < 4; i++)
        #pragma unroll
        for (int k = 0; k < 4; k++) po[i][k] = 0.f;
    float l0 = 0.f, l1 = 0.f;

    int g     = lane >> 2;
    int colp  = (lane & 3) * 2;
    int trow0 = qb * 128 + 16 * w + g;
    int trow1 = trow0 + 8;

    const __nv_bfloat16* kgbase = g_qkvh + ((size_t)b * T_TOK) * QKS + 256;
    const __nv_bfloat16* vwbase = g_vw + (size_t)b * T_TOK * PATCH;

    int jmax = 2 * qb + 1;
    for (int j = 0; j <= jmax; j++) {
        __syncthreads();
        const __nv_bfloat16* kg = kgbase + (size_t)j * 64 * QKS;
        #pragma unroll
        for (int t = 0; t < 8; t++) {
            int idx = tid + t * 256;
            int r = idx >> 5, c = idx & 31;
            *(uint4*)&Ks[r * QSTR + c * 8] = *(const uint4*)(kg + (size_t)r * QKS + c * 8);
        }
        {
            int r = tid >> 2, u = tid & 3;          // 64 rows x 4 x 16B
            *(uint4*)&VWs[r * VWSTR + u * 8] =
                *(const uint4*)(vwbase + (size_t)(j * 64 + r) * PATCH + u * 8);
        }
        __syncthreads();

        // ---- S = Q @ K^T ----
        float sc[8][4];
        #pragma unroll
        for (int nt = 0; nt < 8; nt++)
            #pragma unroll
            for (int k = 0; k < 4; k++) sc[nt][k] = 0.f;

        #pragma unroll
        for (int ks = 0; ks < 16; ks++) {
            uint32_t qa[4];
            ldsm4(qa, qaddr + ks * 32);
            #pragma unroll
            for (int nt2 = 0; nt2 < 4; nt2++) {
                uint32_t kb[4];
                ldsm4(kb, kaddr + nt2 * (16 * QSTR * 2) + ks * 32);
                mma16816(sc[2 * nt2],     qa, kb[0], kb[1]);
                mma16816(sc[2 * nt2 + 1], qa, kb[2], kb[3]);
            }
        }

        // ---- fixed-offset softmax + pack P into A-fragments ----
        uint32_t pa[4][4];
        int keyb = j * 64;
        #pragma unroll
        for (int nt = 0; nt < 8; nt++) {
            int k0 = keyb + nt * 8 + colp;
            float p0 = (k0     <= trow0) ? __expf(sc[nt][0] * 0.0625f - 12.0f) : 0.f;
            float p1 = (k0 + 1 <= trow0) ? __expf(sc[nt][1] * 0.0625f - 12.0f) : 0.f;
            float p2 = (k0     <= trow1) ? __expf(sc[nt][2] * 0.0625f - 12.0f) : 0.f;
            float p3 = (k0 + 1 <= trow1) ? __expf(sc[nt][3] * 0.0625f - 12.0f) : 0.f;
            l0 += p0 + p1;
            l1 += p2 + p3;
            int ks = nt >> 1, h = (nt & 1) * 2;
            pa[ks][h]     = packbf2(p0, p1);
            pa[ks][h + 1] = packbf2(p2, p3);
        }

        // ---- predraw += P @ VW : N=32, B via trans ldmatrix from [k][p] ----
        #pragma unroll
        for (int ks = 0; ks < 4; ks++) {
            #pragma unroll
            for (int pt2 = 0; pt2 < 2; pt2++) {
                uint32_t vb[4];
                ldsm4t(vb, vaddr + ks * (16 * VWSTR * 2) + pt2 * 32);
                mma16816(po[2 * pt2],     pa[ks], vb[0], vb[1]);
                mma16816(po[2 * pt2 + 1], pa[ks], vb[2], vb[3]);
            }
        }
    }

    // ---- epilogue: row sums, pred, MSE ----
    l0 += __shfl_xor_sync(0xffffffffu, l0, 1);
    l0 += __shfl_xor_sync(0xffffffffu, l0, 2);
    l1 += __shfl_xor_sync(0xffffffffu, l1, 1);
    l1 += __shfl_xor_sync(0xffffffffu, l1, 2);
    float linv0 = 1.0f / l0, linv1 = 1.0f / l1;

    const float* pbase = g_patches + (size_t)b * L_SER;
    float lsum = 0.f;
    if (trow0 < T_TOK - 1) {
        const float* tgt = pbase + (size_t)(trow0 + 1) * PATCH;
        #pragma unroll
        for (int nt = 0; nt < 4; nt++) {
            int pc = nt * 8 + colp;
            float d0 = po[nt][0] * linv0 + g_bph[pc]     - tgt[pc];
            float d1 = po[nt][1] * linv0 + g_bph[pc + 1] - tgt[pc + 1];
            lsum = fmaf(d0, d0, lsum);
            lsum = fmaf(d1, d1, lsum);
        }
    }
    if (trow1 < T_TOK - 1) {
        const float* tgt = pbase + (size_t)(trow1 + 1) * PATCH;
        #pragma unroll
        for (int nt = 0; nt < 4; nt++) {
            int pc = nt * 8 + colp;
            float d0 = po[nt][2] * linv1 + g_bph[pc]     - tgt[pc];
            float d1 = po[nt][3] * linv1 + g_bph[pc + 1] - tgt[pc + 1];
            lsum = fmaf(d0, d0, lsum);
            lsum = fmaf(d1, d1, lsum);
        }
    }
    #pragma unroll
    for (int s = 16; s >= 1; s >>= 1)
        lsum += __shfl_xor_sync(0xffffffffu, lsum, s);
    if (lane == 0) red[w] = lsum;
    __syncthreads();
    if (tid == 0) {
        float t = 0.f;
        #pragma unroll
        for (int i = 0; i < 8; i++) t += red[i];
        atomicAdd(&g_loss_acc, (double)t);
    }
}

// ---------------------------------------------------------------------------
// K6: finalize
// ---------------------------------------------------------------------------
__global__ void finalize_kernel(float* out)
{
    out[0] = (float)(g_loss_acc / (double)(BATCH * (T_TOK - 1) * PATCH));
}

// ---------------------------------------------------------------------------
// Launch
// ---------------------------------------------------------------------------
extern "C" void kernel_launch(void* const* d_in, const int* in_sizes, int n_in,
                              void* d_out, int out_size)
{
    const float* x      = (const float*)d_in[0];
    const float* Wproj  = (const float*)d_in[1];
    const float* bproj  = (const float*)d_in[2];
    const float* Wqkv   = (const float*)d_in[3];
    const float* bqkv   = (const float*)d_in[4];
    const float* Wout   = (const float*)d_in[5];
    const float* bout   = (const float*)d_in[6];
    const float* Whead  = (const float*)d_in[7];
    const float* bhead  = (const float*)d_in[8];
    float* out = (float*)d_out;

    cudaFuncSetAttribute(attention_kernel,
                         cudaFuncAttributeMaxDynamicSharedMemorySize, ATTN_SMEM_BYTES);

    prep_kernel<<<132, 256>>>(Wproj, bproj, Wqkv, bqkv, Wout, bout, Whead, bhead);
    prep2_kernel<<<1, 1024>>>();
    instnorm_stats<<<128, 256>>>(x);
    instnorm_apply<<<128, 256>>>(x);
    qkv_gemm_kernel<<<dim3(9, ROWS / 64), 256>>>();
    attention_kernel<<<256, 256, ATTN_SMEM_BYTES>>>();
    finalize_kernel<<<1, 1>>>(out);
}

// round 14
// speedup vs baseline: 6.1242x; 1.3432x over previous
#include <cuda_runtime.h>
#include <cuda_bf16.h>
#include <math.h>
#include <stdint.h>

// ---------------------------------------------------------------------------
// Problem constants
// ---------------------------------------------------------------------------
#define BATCH   32
#define L_SER   32768
#define PATCH   32
#define DMODEL  256
#define T_TOK   1024
#define QKV_N   768
#define QKS     512            // Q,K row stride in g_qkvh
#define ROWS    (BATCH * T_TOK)

// ---------------------------------------------------------------------------
// Device scratch
// ---------------------------------------------------------------------------
__device__ float          g_patches[BATCH * L_SER];          // fp32 (MSE targets + GEMM A)
__device__ __nv_bfloat16  g_qkvh[(size_t)ROWS * QKS];        // 32 MB bf16 Q|K
__device__ __nv_bfloat16  g_vw[(size_t)ROWS * PATCH];        // 2 MB  VW [t][p]
__device__ float          g_Weff[PATCH * QKV_N];
__device__ float          g_beff[QKV_N];
__device__ float          g_Wph[DMODEL * PATCH];
__device__ float          g_bph[PATCH];
__device__ float          g_Wvw[PATCH * PATCH];
__device__ float          g_bvw[PATCH];
__device__ double         g_stats[2 * BATCH];
__device__ double         g_loss_acc;

// ---------------------------------------------------------------------------
// mma.sync / ldmatrix / cp.async helpers
// ---------------------------------------------------------------------------
__device__ __forceinline__ uint32_t s2u(const void* p) {
    return (uint32_t)__cvta_generic_to_shared(p);
}
__device__ __forceinline__ void ldsm4(uint32_t* r, uint32_t a) {
    asm volatile("ldmatrix.sync.aligned.m8n8.x4.shared.b16 {%0,%1,%2,%3}, [%4];"
                 : "=r"(r[0]), "=r"(r[1]), "=r"(r[2]), "=r"(r[3]) : "r"(a));
}
__device__ __forceinline__ void ldsm4t(uint32_t* r, uint32_t a) {
    asm volatile("ldmatrix.sync.aligned.m8n8.x4.trans.shared.b16 {%0,%1,%2,%3}, [%4];"
                 : "=r"(r[0]), "=r"(r[1]), "=r"(r[2]), "=r"(r[3]) : "r"(a));
}
__device__ __forceinline__ void mma16816(float* c, const uint32_t* a, uint32_t b0, uint32_t b1) {
    asm volatile("mma.sync.aligned.m16n8k16.row.col.f32.bf16.bf16.f32 "
                 "{%0,%1,%2,%3}, {%4,%5,%6,%7}, {%8,%9}, {%0,%1,%2,%3};"
                 : "+f"(c[0]), "+f"(c[1]), "+f"(c[2]), "+f"(c[3])
                 : "r"(a[0]), "r"(a[1]), "r"(a[2]), "r"(a[3]), "r"(b0), "r"(b1));
}
__device__ __forceinline__ uint32_t packbf2(float x, float y) {
    __nv_bfloat162 h = __float22bfloat162_rn(make_float2(x, y));
    return *(uint32_t*)&h;
}
__device__ __forceinline__ void cp16(uint32_t s, const void* g) {
    asm volatile("cp.async.cg.shared.global [%0], [%1], 16;"
                 :: "r"(s), "l"(__cvta_generic_to_global(g)) : "memory");
}
#define CPCOMMIT() asm volatile("cp.async.commit_group;" ::: "memory")
#define CPWAIT(n)  asm volatile("cp.async.wait_group %0;" :: "n"(n) : "memory")

// ---------------------------------------------------------------------------
// K1: fold weights + zero accumulators
// ---------------------------------------------------------------------------
__global__ void prep_kernel(const float* __restrict__ Wproj, const float* __restrict__ bproj,
                            const float* __restrict__ Wqkv,  const float* __restrict__ bqkv,
                            const float* __restrict__ Wout,  const float* __restrict__ bout,
                            const float* __restrict__ Whead, const float* __restrict__ bhead)
{
    int idx = blockIdx.x * blockDim.x + threadIdx.x;
    if (idx == 0) g_loss_acc = 0.0;
    if (idx < 2 * BATCH) g_stats[idx] = 0.0;

    if (idx < PATCH * QKV_N) {
        int k = idx / QKV_N, j = idx % QKV_N;
        float acc = 0.f;
        #pragma unroll 8
        for (int d = 0; d < DMODEL; d++)
            acc = fmaf(Wproj[k * DMODEL + d], Wqkv[d * QKV_N + j], acc);
        g_Weff[idx] = acc;
    } else if (idx < PATCH * QKV_N + QKV_N) {
        int j = idx - PATCH * QKV_N;
        float acc = bqkv[j];
        #pragma unroll 8
        for (int d = 0; d < DMODEL; d++)
            acc = fmaf(bproj[d], Wqkv[d * QKV_N + j], acc);
        g_beff[j] = acc;
    } else if (idx < PATCH * QKV_N + QKV_N + DMODEL * PATCH) {
        int t = idx - (PATCH * QKV_N + QKV_N);
        int d = t / PATCH, p = t % PATCH;
        float acc = 0.f;
        #pragma unroll 8
        for (int e = 0; e < DMODEL; e++)
            acc = fmaf(Wout[d * DMODEL + e], Whead[e * PATCH + p], acc);
        g_Wph[t] = acc;
    } else if (idx < PATCH * QKV_N + QKV_N + DMODEL * PATCH + PATCH) {
        int p = idx - (PATCH * QKV_N + QKV_N + DMODEL * PATCH);
        float acc = bhead[p];
        #pragma unroll 8
        for (int e = 0; e < DMODEL; e++)
            acc = fmaf(bout[e], Whead[e * PATCH + p], acc);
        g_bph[p] = acc;
    }
}

// ---------------------------------------------------------------------------
// K1b: Wvw = Weff[:,512:768] @ Wph;  bvw = beff[512:] @ Wph
// ---------------------------------------------------------------------------
__global__ __launch_bounds__(1024) void prep2_kernel()
{
    int tid = threadIdx.x;
    int k = tid >> 5, p = tid & 31;
    float acc = 0.f;
    #pragma unroll 8
    for (int d = 0; d < DMODEL; d++)
        acc = fmaf(g_Weff[k * QKV_N + 512 + d], g_Wph[d * PATCH + p], acc);
    g_Wvw[k * PATCH + p] = acc;
    if (tid < PATCH) {
        float b = 0.f;
        #pragma unroll 8
        for (int d = 0; d < DMODEL; d++)
            b = fmaf(g_beff[512 + d], g_Wph[d * PATCH + tid], b);
        g_bvw[tid] = b;
    }
}

// ---------------------------------------------------------------------------
// K2a/K2b: two-pass instance norm, 512 CTAs each (16 per batch row)
// ---------------------------------------------------------------------------
__global__ __launch_bounds__(256) void instnorm_stats(const float* __restrict__ x)
{
    int b = blockIdx.x >> 4, part = blockIdx.x & 15;
    int tid = threadIdx.x;
    const float* xr = x + (size_t)b * L_SER + part * 2048;

    float s = 0.f, ss = 0.f;
    #pragma unroll
    for (int t = 0; t < 2; t++) {
        float4 v = *(const float4*)(xr + tid * 4 + t * 1024);
        s  += v.x + v.y + v.z + v.w;
        ss += v.x * v.x + v.y * v.y + v.z * v.z + v.w * v.w;
    }
    #pragma unroll
    for (int w = 16; w >= 1; w >>= 1) {
        s  += __shfl_xor_sync(0xffffffffu, s,  w);
        ss += __shfl_xor_sync(0xffffffffu, ss, w);
    }
    __shared__ float rs[8], rss[8];
    int lane = tid & 31, warp = tid >> 5;
    if (lane == 0) { rs[warp] = s; rss[warp] = ss; }
    __syncthreads();
    if (tid == 0) {
        float ts = 0.f, tss = 0.f;
        #pragma unroll
        for (int w = 0; w < 8; w++) { ts += rs[w]; tss += rss[w]; }
        atomicAdd(&g_stats[2 * b],     (double)ts);
        atomicAdd(&g_stats[2 * b + 1], (double)tss);
    }
}

__global__ __launch_bounds__(256) void instnorm_apply(const float* __restrict__ x)
{
    int b = blockIdx.x >> 4, part = blockIdx.x & 15;
    int tid = threadIdx.x;
    double s  = g_stats[2 * b];
    double ss = g_stats[2 * b + 1];
    double meand = s / (double)L_SER;
    double vard  = (ss - (double)L_SER * meand * meand) / (double)(L_SER - 1);
    float mean = (float)meand;
    float inv  = 1.0f / ((float)sqrt(vard) + 1e-5f);

    const float* xr = x + (size_t)b * L_SER + part * 2048;
    float*       pr = g_patches + (size_t)b * L_SER + part * 2048;
    #pragma unroll
    for (int t = 0; t < 2; t++) {
        float4 v = *(const float4*)(xr + tid * 4 + t * 1024);
        v.x = (v.x - mean) * inv; v.y = (v.y - mean) * inv;
        v.z = (v.z - mean) * inv; v.w = (v.w - mean) * inv;
        *(float4*)(pr + tid * 4 + t * 1024) = v;
    }
}

// ---------------------------------------------------------------------------
// K3: [Q|K|VW] = patches @ [Weff_qk | Wvw] + bias via mma.sync bf16.
//   One CTA per 128-row block; A staged once; 9 col-blocks streamed.
// ---------------------------------------------------------------------------
#define ASTR 40
#define BSTR 72

__global__ __launch_bounds__(256) void qkv_tc_kernel()
{
    __shared__ __align__(16) __nv_bfloat16 As[128 * ASTR];   // 10.2 KB
    __shared__ __align__(16) __nv_bfloat16 Bs[32 * BSTR];    //  4.6 KB

    int tid = threadIdx.x;
    int w = tid >> 5, lane = tid & 31;
    int wr = w & 3, wc = w >> 2;
    int row0 = blockIdx.x * 128;

    // stage A (fp32 -> bf16): 128 rows x 16 float2
    #pragma unroll
    for (int t = 0; t < 8; t++) {
        int idx = tid + t * 256;
        int r = idx >> 4, c2 = idx & 15;
        float2 v = *(const float2*)(g_patches + (size_t)(row0 + r) * PATCH + c2 * 2);
        *(uint32_t*)&As[r * ASTR + c2 * 2] = packbf2(v.x, v.y);
    }
    __syncthreads();

    // A fragments (hoisted): [mt][ks][4]
    uint32_t af[2][2][4];
    uint32_t aaddr = s2u(&As[(wr * 32 + (lane & 15)) * ASTR + ((lane >> 4) << 3)]);
    #pragma unroll
    for (int mt = 0; mt < 2; mt++)
        #pragma unroll
        for (int ks = 0; ks < 2; ks++)
            ldsm4(af[mt][ks], aaddr + mt * (16 * ASTR * 2) + ks * 32);

    uint32_t baddr = s2u(&Bs[((lane & 7) + (((lane >> 3) & 1) << 3)) * BSTR
                             + wc * 32 + ((lane >> 4) << 3)]);

    for (int cb = 0; cb < 9; cb++) {
        __syncthreads();          // prev B consumed
        // stage B (fp32 -> bf16): 32 k-rows x 32 float2
        #pragma unroll
        for (int t = 0; t < 4; t++) {
            int idx = tid + t * 256;
            int k = idx >> 5, c2 = idx & 31;
            float2 v;
            if (cb < 8)      v = *(const float2*)(g_Weff + k * QKV_N + cb * 64 + c2 * 2);
            else if (c2 < 16) v = *(const float2*)(g_Wvw + k * PATCH + c2 * 2);
            else              v = make_float2(0.f, 0.f);
            *(uint32_t*)&Bs[k * BSTR + c2 * 2] = packbf2(v.x, v.y);
        }
        __syncthreads();

        float c[2][4][4];
        #pragma unroll
        for (int mt = 0; mt < 2; mt++)
            #pragma unroll
            for (int nt = 0; nt < 4; nt++)
                #pragma unroll
                for (int q = 0; q < 4; q++) c[mt][nt][q] = 0.f;

        #pragma unroll
        for (int ks = 0; ks < 2; ks++)
            #pragma unroll
            for (int nt2 = 0; nt2 < 2; nt2++) {
                uint32_t vb[4];
                ldsm4t(vb, baddr + ks * (16 * BSTR * 2) + nt2 * 32);
                #pragma unroll
                for (int mt = 0; mt < 2; mt++) {
                    mma16816(c[mt][nt2 * 2],     af[mt][ks], vb[0], vb[1]);
                    mma16816(c[mt][nt2 * 2 + 1], af[mt][ks], vb[2], vb[3]);
                }
            }

        // epilogue for this col-block
        int colp = (lane & 3) * 2;
        #pragma unroll
        for (int mt = 0; mt < 2; mt++) {
            int r0 = row0 + wr * 32 + mt * 16 + (lane >> 2);
            #pragma unroll
            for (int nt = 0; nt < 4; nt++) {
                int col = wc * 32 + nt * 8 + colp;
                if (cb < 8) {
                    int gcol = cb * 64 + col;
                    float b0 = g_beff[gcol], b1 = g_beff[gcol + 1];
                    *(uint32_t*)&g_qkvh[(size_t)r0 * QKS + gcol] =
                        packbf2(c[mt][nt][0] + b0, c[mt][nt][1] + b1);
                    *(uint32_t*)&g_qkvh[(size_t)(r0 + 8) * QKS + gcol] =
                        packbf2(c[mt][nt][2] + b0, c[mt][nt][3] + b1);
                } else if (wc == 0) {
                    float b0 = g_bvw[col], b1 = g_bvw[col + 1];
                    *(uint32_t*)&g_vw[(size_t)r0 * PATCH + col] =
                        packbf2(c[mt][nt][0] + b0, c[mt][nt][1] + b1);
                    *(uint32_t*)&g_vw[(size_t)(r0 + 8) * PATCH + col] =
                        packbf2(c[mt][nt][2] + b0, c[mt][nt][3] + b1);
                }
            }
        }
    }
}

// ---------------------------------------------------------------------------
// K4: mma.sync bf16 causal attention, BM=128, BN=64, fused head + MSE.
//   cp.async double-buffered K/VW; Q fragments hoisted to registers.
// ---------------------------------------------------------------------------
#define QSTR  264
#define VWSTR 40
#define KTILE_B  (64 * QSTR * 2)     // 33792 bytes per K buffer
#define VWTILE_B (64 * VWSTR * 2)    // 5120 bytes per VW buffer
#define ATTN_SMEM_BYTES ((128 * QSTR + 2 * 64 * QSTR + 2 * 64 * VWSTR) * 2 + 128)

__global__ __launch_bounds__(256, 1) void attention_kernel()
{
    extern __shared__ __align__(16) __nv_bfloat16 smh[];
    __nv_bfloat16* Qs  = smh;                        // [128][QSTR]
    __nv_bfloat16* Ks  = Qs + 128 * QSTR;            // [2][64][QSTR]
    __nv_bfloat16* VWs = Ks + 2 * 64 * QSTR;         // [2][64][VWSTR]
    float* red = (float*)(VWs + 2 * 64 * VWSTR);

    int tid  = threadIdx.x;
    int w    = tid >> 5, lane = tid & 31;
    int qb   = 7 - (blockIdx.x >> 5);                // heavy q-blocks first
    int b    = blockIdx.x & 31;

    const __nv_bfloat16* kgbase = g_qkvh + ((size_t)b * T_TOK) * QKS + 256;
    const __nv_bfloat16* vwbase = g_vw + (size_t)b * T_TOK * PATCH;

    uint32_t ks_u32 = s2u(Ks);
    uint32_t vw_u32 = s2u(VWs);

    // prologue: prefetch j=0 into buffer 0
    {
        const __nv_bfloat16* kg = kgbase;
        #pragma unroll
        for (int t = 0; t < 8; t++) {
            int idx = tid + t * 256;
            int r = idx >> 5, c = idx & 31;
            cp16(ks_u32 + (uint32_t)(r * QSTR + c * 8) * 2, kg + (size_t)r * QKS + c * 8);
        }
        int r = tid >> 2, u = tid & 3;
        cp16(vw_u32 + (uint32_t)(r * VWSTR + u * 8) * 2, vwbase + (size_t)r * PATCH + u * 8);
        CPCOMMIT();
    }

    // load Q [128,256]
    const __nv_bfloat16* qg = g_qkvh + ((size_t)b * T_TOK + qb * 128) * QKS;
    #pragma unroll
    for (int t = 0; t < 16; t++) {
        int idx = tid + t * 256;
        int r = idx >> 5, c = idx & 31;
        *(uint4*)&Qs[r * QSTR + c * 8] = *(const uint4*)(qg + (size_t)r * QKS + c * 8);
    }
    __syncthreads();

    // hoist Q fragments: [16 ks][4]
    uint32_t qa[16][4];
    uint32_t qaddr = s2u(&Qs[(16 * w + (lane & 15)) * QSTR + ((lane >> 4) << 3)]);
    #pragma unroll
    for (int ks = 0; ks < 16; ks++) ldsm4(qa[ks], qaddr + ks * 32);

    uint32_t kaddr0 = ks_u32 + (((lane & 7) + ((lane >> 4) << 3)) * QSTR + (((lane >> 3) & 1) << 3)) * 2;
    uint32_t vaddr0 = vw_u32 + (((lane & 7) + (((lane >> 3) & 1) << 3)) * VWSTR + ((lane >> 4) << 3)) * 2;

    float po[4][4];
    #pragma unroll
    for (int i = 0; i < 4; i++)
        #pragma unroll
        for (int k = 0; k < 4; k++) po[i][k] = 0.f;
    float l0 = 0.f, l1 = 0.f;

    int g     = lane >> 2;
    int colp  = (lane & 3) * 2;
    int trow0 = qb * 128 + 16 * w + g;
    int trow1 = trow0 + 8;

    int jmax = 2 * qb + 1;
    for (int j = 0; j <= jmax; j++) {
        __syncthreads();          // all warps done with buffer (j+1)&1 (j-1's data)
        if (j < jmax) {
            const __nv_bfloat16* kg = kgbase + (size_t)(j + 1) * 64 * QKS;
            uint32_t kd = ks_u32 + ((j + 1) & 1) * KTILE_B;
            #pragma unroll
            for (int t = 0; t < 8; t++) {
                int idx = tid + t * 256;
                int r = idx >> 5, c = idx & 31;
                cp16(kd + (uint32_t)(r * QSTR + c * 8) * 2, kg + (size_t)r * QKS + c * 8);
            }
            const __nv_bfloat16* vg = vwbase + (size_t)(j + 1) * 64 * PATCH;
            uint32_t vd = vw_u32 + ((j + 1) & 1) * VWTILE_B;
            int r = tid >> 2, u = tid & 3;
            cp16(vd + (uint32_t)(r * VWSTR + u * 8) * 2, vg + (size_t)r * PATCH + u * 8);
            CPCOMMIT();
            CPWAIT(1);            // current j's data complete
        } else {
            CPWAIT(0);
        }
        __syncthreads();          // arrival visible

        uint32_t kaddr = kaddr0 + (j & 1) * KTILE_B;
        uint32_t vaddr = vaddr0 + (j & 1) * VWTILE_B;

        // ---- S = Q @ K^T ----
        float sc[8][4];
        #pragma unroll
        for (int nt = 0; nt < 8; nt++)
            #pragma unroll
            for (int k = 0; k < 4; k++) sc[nt][k] = 0.f;

        #pragma unroll
        for (int ks = 0; ks < 16; ks++) {
            #pragma unroll
            for (int nt2 = 0; nt2 < 4; nt2++) {
                uint32_t kb[4];
                ldsm4(kb, kaddr + nt2 * (16 * QSTR * 2) + ks * 32);
                mma16816(sc[2 * nt2],     qa[ks], kb[0], kb[1]);
                mma16816(sc[2 * nt2 + 1], qa[ks], kb[2], kb[3]);
            }
        }

        // ---- fixed-offset softmax + pack P into A-fragments ----
        uint32_t pa[4][4];
        int keyb = j * 64;
        #pragma unroll
        for (int nt = 0; nt < 8; nt++) {
            int k0 = keyb + nt * 8 + colp;
            float p0 = (k0     <= trow0) ? __expf(sc[nt][0] * 0.0625f - 12.0f) : 0.f;
            float p1 = (k0 + 1 <= trow0) ? __expf(sc[nt][1] * 0.0625f - 12.0f) : 0.f;
            float p2 = (k0     <= trow1) ? __expf(sc[nt][2] * 0.0625f - 12.0f) : 0.f;
            float p3 = (k0 + 1 <= trow1) ? __expf(sc[nt][3] * 0.0625f - 12.0f) : 0.f;
            l0 += p0 + p1;
            l1 += p2 + p3;
            int ks = nt >> 1, h = (nt & 1) * 2;
            pa[ks][h]     = packbf2(p0, p1);
            pa[ks][h + 1] = packbf2(p2, p3);
        }

        // ---- predraw += P @ VW : N=32, B via trans ldmatrix ----
        #pragma unroll
        for (int ks = 0; ks < 4; ks++) {
            #pragma unroll
            for (int pt2 = 0; pt2 < 2; pt2++) {
                uint32_t vb[4];
                ldsm4t(vb, vaddr + ks * (16 * VWSTR * 2) + pt2 * 32);
                mma16816(po[2 * pt2],     pa[ks], vb[0], vb[1]);
                mma16816(po[2 * pt2 + 1], pa[ks], vb[2], vb[3]);
            }
        }
    }

    // ---- epilogue: row sums, pred, MSE ----
    l0 += __shfl_xor_sync(0xffffffffu, l0, 1);
    l0 += __shfl_xor_sync(0xffffffffu, l0, 2);
    l1 += __shfl_xor_sync(0xffffffffu, l1, 1);
    l1 += __shfl_xor_sync(0xffffffffu, l1, 2);
    float linv0 = 1.0f / l0, linv1 = 1.0f / l1;

    const float* pbase = g_patches + (size_t)b * L_SER;
    float lsum = 0.f;
    if (trow0 < T_TOK - 1) {
        const float* tgt = pbase + (size_t)(trow0 + 1) * PATCH;
        #pragma unroll
        for (int nt = 0; nt < 4; nt++) {
            int pc = nt * 8 + colp;
            float d0 = po[nt][0] * linv0 + g_bph[pc]     - tgt[pc];
            float d1 = po[nt][1] * linv0 + g_bph[pc + 1] - tgt[pc + 1];
            lsum = fmaf(d0, d0, lsum);
            lsum = fmaf(d1, d1, lsum);
        }
    }
    if (trow1 < T_TOK - 1) {
        const float* tgt = pbase + (size_t)(trow1 + 1) * PATCH;
        #pragma unroll
        for (int nt = 0; nt < 4; nt++) {
            int pc = nt * 8 + colp;
            float d0 = po[nt][2] * linv1 + g_bph[pc]     - tgt[pc];
            float d1 = po[nt][3] * linv1 + g_bph[pc + 1] - tgt[pc + 1];
            lsum = fmaf(d0, d0, lsum);
            lsum = fmaf(d1, d1, lsum);
        }
    }
    #pragma unroll
    for (int s = 16; s >= 1; s >>= 1)
        lsum += __shfl_xor_sync(0xffffffffu, lsum, s);
    if (lane == 0) red[w] = lsum;
    __syncthreads();
    if (tid == 0) {
        float t = 0.f;
        #pragma unroll
        for (int i = 0; i < 8; i++) t += red[i];
        atomicAdd(&g_loss_acc, (double)t);
    }
}

// ---------------------------------------------------------------------------
// K6: finalize
// ---------------------------------------------------------------------------
__global__ void finalize_kernel(float* out)
{
    out[0] = (float)(g_loss_acc / (double)(BATCH * (T_TOK - 1) * PATCH));
}

// ---------------------------------------------------------------------------
// Launch
// ---------------------------------------------------------------------------
extern "C" void kernel_launch(void* const* d_in, const int* in_sizes, int n_in,
                              void* d_out, int out_size)
{
    const float* x      = (const float*)d_in[0];
    const float* Wproj  = (const float*)d_in[1];
    const float* bproj  = (const float*)d_in[2];
    const float* Wqkv   = (const float*)d_in[3];
    const float* bqkv   = (const float*)d_in[4];
    const float* Wout   = (const float*)d_in[5];
    const float* bout   = (const float*)d_in[6];
    const float* Whead  = (const float*)d_in[7];
    const float* bhead  = (const float*)d_in[8];
    float* out = (float*)d_out;

    cudaFuncSetAttribute(attention_kernel,
                         cudaFuncAttributeMaxDynamicSharedMemorySize, ATTN_SMEM_BYTES);

    prep_kernel<<<132, 256>>>(Wproj, bproj, Wqkv, bqkv, Wout, bout, Whead, bhead);
    prep2_kernel<<<1, 1024>>>();
    instnorm_stats<<<512, 256>>>(x);
    instnorm_apply<<<512, 256>>>(x);
    qkv_tc_kernel<<<256, 256>>>();
    attention_kernel<<<256, 256, ATTN_SMEM_BYTES>>>();
    finalize_kernel<<<1, 1>>>(out);
}